// round 5
// baseline (speedup 1.0000x reference)
#include <cuda_runtime.h>
#include <cstdint>

// ---------------------------------------------------------------------------
// TopKRouter: logits = x @ gate_w^T (16384 x 2048 x 64) via EXACT bf16x3
// split (6 products) on mma.sync.m16n8k16.bf16. Near-tie tokens re-derive
// their candidate logits bit-exactly in the R1 (known-passing) summation
// order and re-decide. Fused softmax/top-2/aux epilogue, single launch.
// Output (fp32): [top_indices (BS*2)] [top_weights (BS*2)] [aux ...fill]
// ---------------------------------------------------------------------------

#define NEXP 64
#define DIM  2048
#define KC   32                 // K per chunk
#define TM   128                // tokens per CTA
#define NCH  (DIM / KC)         // 64 chunks
#define RSTR 20                 // row stride in 32-bit words (80B): LDS conflict-free
#define XT_W (TM * RSTR)        // 2560 words per x chunk tile
#define WT_W (NEXP * RSTR)      // 1280 words per w chunk tile
#define WBASE (3 * XT_W)        // w tiles after 3 x tiles
#define STW  (3 * XT_W + 3 * WT_W)   // 11520 words per stage (46080 B)
#define MAXBLK 256
#define AMB_THR 2e-5f           // ambiguity trigger (16 sigma of MMA acc error)

__device__ float    g_Pblk[MAXBLK * NEXP];
__device__ float    g_zblk[MAXBLK];
__device__ int      g_cntblk[MAXBLK * NEXP];
__device__ unsigned g_arrival;          // zero at load; last block resets each run

#define MMA_BF16(d, a, b) \
    asm volatile("mma.sync.aligned.m16n8k16.row.col.f32.bf16.bf16.f32 " \
                 "{%0,%1,%2,%3}, {%4,%5,%6,%7}, {%8,%9}, {%0,%1,%2,%3};" \
                 : "+f"((d)[0]), "+f"((d)[1]), "+f"((d)[2]), "+f"((d)[3]) \
                 : "r"((a)[0]), "r"((a)[1]), "r"((a)[2]), "r"((a)[3]), \
                   "r"((b)[0]), "r"((b)[1]))

// Exact 3-way bf16 split: v == c1 + c2 + c3 (bit-exact; 8+8+8 significand bits).
static __device__ __forceinline__ void split3(float v, uint32_t& c1, uint32_t& c2, uint32_t& c3) {
    uint32_t m1 = __float_as_uint(v) & 0xFFFF0000u;
    float r1 = v - __uint_as_float(m1);
    uint32_t m2 = __float_as_uint(r1) & 0xFFFF0000u;
    float r2 = r1 - __uint_as_float(m2);          // <= 8 significant bits: exact bf16
    c1 = m1; c2 = m2; c3 = __float_as_uint(r2);
}
static __device__ __forceinline__ uint32_t pk(uint32_t e, uint32_t o) {
    uint32_t d;
    asm("prmt.b32 %0, %1, %2, 0x7632;" : "=r"(d) : "r"(e), "r"(o));
    return d;
}
static __device__ __forceinline__ void store3(uint32_t* base0, int tile_w, float4 v) {
    uint32_t c1[4], c2[4], c3[4];
    split3(v.x, c1[0], c2[0], c3[0]);
    split3(v.y, c1[1], c2[1], c3[1]);
    split3(v.z, c1[2], c2[2], c3[2]);
    split3(v.w, c1[3], c2[3], c3[3]);
    *(uint2*)(base0 + 0 * tile_w) = make_uint2(pk(c1[0], c1[1]), pk(c1[2], c1[3]));
    *(uint2*)(base0 + 1 * tile_w) = make_uint2(pk(c2[0], c2[1]), pk(c2[2], c2[3]));
    *(uint2*)(base0 + 2 * tile_w) = make_uint2(pk(c3[0], c3[1]), pk(c3[2], c3[3]));
}

__global__ void __launch_bounds__(256, 1)
router_bf16x3(const float* __restrict__ X, const float* __restrict__ W,
              float* __restrict__ out, int BS, int out_size, int nblk)
{
    extern __shared__ uint32_t smw[];
    __shared__ int s_flag;

    const int tid  = threadIdx.x;
    const int wid  = tid >> 5;
    const int lane = tid & 31;
    const int blk  = blockIdx.x;
    const int tok0 = blk * TM;

    // ---- producer mapping ----
    const int lrow = tid >> 3;
    const int lcol = (tid & 7) * 4;
    const float* Xg = X + (size_t)(tok0 + lrow) * DIM + lcol;
    const float* Wg = W + (size_t)lrow * DIM + lcol;

    float4 xb[2][4];
    float4 wb[2][2];
    #pragma unroll
    for (int r = 0; r < 4; r++) xb[0][r] = *(const float4*)(Xg + (size_t)(32 * r) * DIM);
    #pragma unroll
    for (int r = 0; r < 2; r++) wb[0][r] = *(const float4*)(Wg + (size_t)(32 * r) * DIM);

    // ---- consumer mapping: warp tile m32 x n32 ----
    const int wm = wid & 3;
    const int wn = wid >> 2;
    const int qr = lane >> 2;
    const int qc = lane & 3;

    float acc[2][4][4];
    #pragma unroll
    for (int i = 0; i < 2; i++)
        #pragma unroll
        for (int j = 0; j < 4; j++)
            #pragma unroll
            for (int r = 0; r < 4; r++) acc[i][j][r] = 0.f;

    for (int c = 0; c < NCH; c++) {
        const int buf = c & 1;
        if (c + 1 < NCH) {
            const int k0 = (c + 1) * KC;
            #pragma unroll
            for (int r = 0; r < 4; r++)
                xb[buf ^ 1][r] = *(const float4*)(Xg + k0 + (size_t)(32 * r) * DIM);
            #pragma unroll
            for (int r = 0; r < 2; r++)
                wb[buf ^ 1][r] = *(const float4*)(Wg + k0 + (size_t)(32 * r) * DIM);
        }

        uint32_t* sb = smw + (size_t)(c & 1) * STW;
        #pragma unroll
        for (int r = 0; r < 4; r++)
            store3(sb + (lrow + 32 * r) * RSTR + (lcol >> 1), XT_W, xb[buf][r]);
        #pragma unroll
        for (int r = 0; r < 2; r++)
            store3(sb + WBASE + (lrow + 32 * r) * RSTR + (lcol >> 1), WT_W, wb[buf][r]);

        __syncthreads();

        const uint32_t* st = smw + (size_t)(c & 1) * STW;
        #pragma unroll
        for (int s = 0; s < 2; s++) {
            uint32_t bf[3][4][2];
            #pragma unroll
            for (int ch = 0; ch < 3; ch++)
                #pragma unroll
                for (int j = 0; j < 4; j++) {
                    const int base = WBASE + ch * WT_W
                                   + (wn * 32 + j * 8 + qr) * RSTR + qc + 8 * s;
                    bf[ch][j][0] = st[base];
                    bf[ch][j][1] = st[base + 4];
                }
            #pragma unroll
            for (int ch = 0; ch < 3; ch++) {
                uint32_t af[2][4];
                #pragma unroll
                for (int i = 0; i < 2; i++) {
                    const int base = ch * XT_W
                                   + (wm * 32 + i * 16 + qr) * RSTR + qc + 8 * s;
                    af[i][0] = st[base];
                    af[i][1] = st[base + 8 * RSTR];
                    af[i][2] = st[base + 4];
                    af[i][3] = st[base + 8 * RSTR + 4];
                }
                const int nb = (ch == 0) ? 3 : ((ch == 1) ? 2 : 1);
                #pragma unroll
                for (int cb = 0; cb < 3; cb++) {
                    if (cb < nb) {
                        #pragma unroll
                        for (int i = 0; i < 2; i++)
                            #pragma unroll
                            for (int j = 0; j < 4; j++)
                                MMA_BF16(acc[i][j], af[i], bf[cb][j]);
                    }
                }
            }
        }
    }
    __syncthreads();

    // ---------------- epilogue: acc -> smem logits tile ---------------------
    float* lg    = (float*)smw;           // [128][65]
    float* sm_m  = lg + TM * 65;
    float* sm_iv = sm_m + TM;
    int*   scnt  = (int*)(sm_iv + TM);
    float* zac   = (float*)(scnt + NEXP);

    #pragma unroll
    for (int i = 0; i < 2; i++)
        #pragma unroll
        for (int j = 0; j < 4; j++) {
            const int row = wm * 32 + i * 16 + qr;
            const int col = wn * 32 + j * 8 + 2 * qc;
            lg[ row      * 65 + col    ] = acc[i][j][0];
            lg[ row      * 65 + col + 1] = acc[i][j][1];
            lg[(row + 8) * 65 + col    ] = acc[i][j][2];
            lg[(row + 8) * 65 + col + 1] = acc[i][j][3];
        }
    if (tid < NEXP) scnt[tid] = 0;
    if (tid == 0) *zac = 0.f;
    __syncthreads();

    if (tid < TM) {
        const float* row = lg + tid * 65;

        // ---- approx top-4 (strict >, lowest index kept on ties) ----
        float tv[4] = {-3.4e38f, -3.4e38f, -3.4e38f, -3.4e38f};
        int   ti[4] = {0, 0, 0, 0};
        #pragma unroll
        for (int e = 0; e < NEXP; e++) {
            float v = row[e];
            if (v > tv[3]) {
                if (v > tv[0])      { tv[3]=tv[2]; ti[3]=ti[2]; tv[2]=tv[1]; ti[2]=ti[1]; tv[1]=tv[0]; ti[1]=ti[0]; tv[0]=v; ti[0]=e; }
                else if (v > tv[1]) { tv[3]=tv[2]; ti[3]=ti[2]; tv[2]=tv[1]; ti[2]=ti[1]; tv[1]=v;     ti[1]=e; }
                else if (v > tv[2]) { tv[3]=tv[2]; ti[3]=ti[2]; tv[2]=v;     ti[2]=e; }
                else                { tv[3]=v;     ti[3]=e; }
            }
        }

        const float am = tv[0];           // approx max for softmax/aux
        float sum = 0.f;
        #pragma unroll
        for (int e = 0; e < NEXP; e++) sum += __expf(row[e] - am);

        float m = tv[0], m2 = tv[1];
        int   i1 = ti[0], i2 = ti[1];

        // ---- near-tie: recompute candidates bit-exactly in R1's order ----
        if ((tv[0] - tv[1] < AMB_THR) || (tv[1] - tv[2] < AMB_THR)) {
            // sort 4 candidates by expert index ascending (decision replays
            // R1's ascending strict-> scan over these indices)
            int   ci[4] = {ti[0], ti[1], ti[2], ti[3]};
            #pragma unroll
            for (int a = 0; a < 3; a++)
                #pragma unroll
                for (int b = 0; b < 3 - a; b++)
                    if (ci[b] > ci[b + 1]) { int t = ci[b]; ci[b] = ci[b+1]; ci[b+1] = t; }

            const float* xr = X + (size_t)(tok0 + tid) * DIM;
            const float* w0 = W + (size_t)ci[0] * DIM;
            const float* w1 = W + (size_t)ci[1] * DIM;
            const float* w2 = W + (size_t)ci[2] * DIM;
            const float* w3 = W + (size_t)ci[3] * DIM;

            // R1 arithmetic: even-k chain + odd-k chain (sequential fmaf,
            // ascending k), then one add. Bit-exact replay.
            float aE[4] = {0.f, 0.f, 0.f, 0.f};
            float aO[4] = {0.f, 0.f, 0.f, 0.f};
            for (int k = 0; k < DIM; k += 8) {
                #pragma unroll
                for (int u = 0; u < 4; u++) {
                    const int ke = k + 2 * u, ko = ke + 1;
                    const float xe = xr[ke], xo = xr[ko];
                    aE[0] = __fmaf_rn(xe, w0[ke], aE[0]); aO[0] = __fmaf_rn(xo, w0[ko], aO[0]);
                    aE[1] = __fmaf_rn(xe, w1[ke], aE[1]); aO[1] = __fmaf_rn(xo, w1[ko], aO[1]);
                    aE[2] = __fmaf_rn(xe, w2[ke], aE[2]); aO[2] = __fmaf_rn(xo, w2[ko], aO[2]);
                    aE[3] = __fmaf_rn(xe, w3[ke], aE[3]); aO[3] = __fmaf_rn(xo, w3[ko], aO[3]);
                }
            }
            float lex[4];
            #pragma unroll
            for (int c2 = 0; c2 < 4; c2++) lex[c2] = aE[c2] + aO[c2];

            // R1 decision: scan ascending index, strict >
            m = lex[0]; i1 = ci[0];
            #pragma unroll
            for (int c2 = 1; c2 < 4; c2++)
                if (lex[c2] > m) { m = lex[c2]; i1 = ci[c2]; }
            m2 = -3.4e38f; i2 = ci[0];
            #pragma unroll
            for (int c2 = 0; c2 < 4; c2++) {
                if (ci[c2] == i1) continue;
                if (lex[c2] > m2) { m2 = lex[c2]; i2 = ci[c2]; }
            }
        }

        const float e2 = __expf(m2 - m);
        const float r1 = 1.f / (1.f + e2);
        const float r2 = e2 * r1;

        const int tg = tok0 + tid;
        out[2 * tg + 0] = (float)i1;
        out[2 * tg + 1] = (float)i2;
        out[(size_t)2 * BS + 2 * tg + 0] = r1;
        out[(size_t)2 * BS + 2 * tg + 1] = r2;

        sm_m[tid]  = am;
        sm_iv[tid] = 1.f / sum;
        float lse = am + __logf(sum);
        atomicAdd(zac, lse * lse);
        atomicAdd(&scnt[i1], 1);
        atomicAdd(&scnt[i2], 1);
    }
    __syncthreads();

    if (tid < NEXP) {
        float p = 0.f;
        for (int t = 0; t < TM; t++)
            p += __expf(lg[t * 65 + tid] - sm_m[t]) * sm_iv[t];
        g_Pblk[blk * NEXP + tid]   = p;
        g_cntblk[blk * NEXP + tid] = scnt[tid];
    }
    if (tid == 0) g_zblk[blk] = *zac;

    __threadfence();
    __syncthreads();
    if (tid == 0) {
        unsigned v = atomicAdd(&g_arrival, 1u);
        s_flag = (v == (unsigned)(nblk - 1));
    }
    __syncthreads();

    if (s_flag) {                         // last block finalizes (fixed order)
        __threadfence();
        float* sP = lg;
        float* sC = lg + NEXP;
        if (tid < NEXP) {
            float p = 0.f; int cnt = 0;
            for (int b = 0; b < nblk; b++) {
                p   += g_Pblk[b * NEXP + tid];
                cnt += g_cntblk[b * NEXP + tid];
            }
            sP[tid] = p; sC[tid] = (float)cnt;
        }
        __syncthreads();
        if (tid == 0) {
            float z = 0.f;
            for (int b = 0; b < nblk; b++) z += g_zblk[b];
            const float invBSK = 1.f / (2.f * (float)BS);
            const float invBS  = 1.f / (float)BS;
            float bal = 0.f;
            for (int e = 0; e < NEXP; e++)
                bal += (sC[e] * invBSK) * (sP[e] * invBS);
            bal *= (float)NEXP;
            float aux = 0.01f * bal + 0.001f * (z * invBS);
            for (int i = 4 * BS; i < out_size; i++) out[i] = aux;
            g_arrival = 0;                // reset for next replay
        }
    }
}

extern "C" void kernel_launch(void* const* d_in, const int* in_sizes, int n_in,
                              void* d_out, int out_size)
{
    const float* x = (const float*)d_in[0];
    const float* w = (const float*)d_in[1];
    float* out = (float*)d_out;

    const int Dv   = in_sizes[1] / NEXP;   // 2048
    const int BS   = in_sizes[0] / Dv;     // 16384
    const int nblk = BS / TM;              // 128

    const int smem = 2 * STW * (int)sizeof(uint32_t);   // 92160 B
    cudaFuncSetAttribute(router_bf16x3, cudaFuncAttributeMaxDynamicSharedMemorySize, smem);
    router_bf16x3<<<nblk, 256, smem>>>(x, w, out, BS, out_size, nblk);
}

// round 6
// speedup vs baseline: 1.0085x; 1.0085x over previous
#include <cuda_runtime.h>
#include <cstdint>

// ---------------------------------------------------------------------------
// TopKRouter: logits = x @ gate_w^T (16384 x 2048 x 64) via EXACT bf16x3
// split (6 products) on mma.sync.m16n8k16.bf16. 512 threads, 16 warps,
// warp tile m32n32 with 2-way K-split (deterministic smem reduction).
// Near-tie tokens re-derive candidate logits bit-exactly (R1 order).
// Output (fp32): [top_indices (BS*2)] [top_weights (BS*2)] [aux ...fill]
// ---------------------------------------------------------------------------

#define NEXP 64
#define DIM  2048
#define KC   32                 // K per chunk
#define TM   128                // tokens per CTA
#define NCH  (DIM / KC)         // 64 chunks
#define RSTR 20                 // row stride in words (80B): LDS conflict-free
#define XT_W (TM * RSTR)        // 2560 words per x chunk tile
#define WT_W (NEXP * RSTR)      // 1280 words per w chunk tile
#define WBASE (3 * XT_W)
#define STW  (3 * XT_W + 3 * WT_W)   // 11520 words per stage (46080 B)
#define MAXBLK 256
#define AMB_THR 2e-5f

__device__ float    g_Pblk[MAXBLK * NEXP];
__device__ float    g_zblk[MAXBLK];
__device__ int      g_cntblk[MAXBLK * NEXP];
__device__ unsigned g_arrival;

#define MMA_BF16(d, a, b) \
    asm volatile("mma.sync.aligned.m16n8k16.row.col.f32.bf16.bf16.f32 " \
                 "{%0,%1,%2,%3}, {%4,%5,%6,%7}, {%8,%9}, {%0,%1,%2,%3};" \
                 : "+f"((d)[0]), "+f"((d)[1]), "+f"((d)[2]), "+f"((d)[3]) \
                 : "r"((a)[0]), "r"((a)[1]), "r"((a)[2]), "r"((a)[3]), \
                   "r"((b)[0]), "r"((b)[1]))

static __device__ __forceinline__ void split3(float v, uint32_t& c1, uint32_t& c2, uint32_t& c3) {
    uint32_t m1 = __float_as_uint(v) & 0xFFFF0000u;
    float r1 = v - __uint_as_float(m1);
    uint32_t m2 = __float_as_uint(r1) & 0xFFFF0000u;
    float r2 = r1 - __uint_as_float(m2);          // exact: v == c1+c2+c3
    c1 = m1; c2 = m2; c3 = __float_as_uint(r2);
}
static __device__ __forceinline__ uint32_t pk(uint32_t e, uint32_t o) {
    uint32_t d;
    asm("prmt.b32 %0, %1, %2, 0x7632;" : "=r"(d) : "r"(e), "r"(o));
    return d;
}
static __device__ __forceinline__ void store3(uint32_t* base0, int tile_w, float4 v) {
    uint32_t c1[4], c2[4], c3[4];
    split3(v.x, c1[0], c2[0], c3[0]);
    split3(v.y, c1[1], c2[1], c3[1]);
    split3(v.z, c1[2], c2[2], c3[2]);
    split3(v.w, c1[3], c2[3], c3[3]);
    *(uint2*)(base0 + 0 * tile_w) = make_uint2(pk(c1[0], c1[1]), pk(c1[2], c1[3]));
    *(uint2*)(base0 + 1 * tile_w) = make_uint2(pk(c2[0], c2[1]), pk(c2[2], c2[3]));
    *(uint2*)(base0 + 2 * tile_w) = make_uint2(pk(c3[0], c3[1]), pk(c3[2], c3[3]));
}

__global__ void __launch_bounds__(512, 1)
router_bf16x3(const float* __restrict__ X, const float* __restrict__ W,
              float* __restrict__ out, int BS, int out_size, int nblk)
{
    extern __shared__ uint32_t smw[];
    __shared__ int s_flag;

    const int tid  = threadIdx.x;
    const int wid  = tid >> 5;
    const int lane = tid & 31;
    const int blk  = blockIdx.x;
    const int tok0 = blk * TM;

    // ---- producer mapping: 512 threads; x: 2 float4 rows, w: 1 float4 ----
    const int lrow = tid >> 3;            // 0..63
    const int lcol = (tid & 7) * 4;       // k offset 0,4,..28
    const float* Xg = X + (size_t)(tok0 + lrow) * DIM + lcol;
    const float* Wg = W + (size_t)lrow * DIM + lcol;

    float4 xb[2][2];
    float4 wb[2][1];
    #pragma unroll
    for (int r = 0; r < 2; r++) xb[0][r] = *(const float4*)(Xg + (size_t)(64 * r) * DIM);
    wb[0][0] = *(const float4*)(Wg);

    // ---- consumer mapping: 16 warps = 4m x 2n x 2k-split, tile m32n32 ----
    const int wm = wid & 3;               // m group (m32)
    const int wn = (wid >> 2) & 1;        // n group (n32)
    const int ks = wid >> 3;              // k16 half of each chunk
    const int qr = lane >> 2;
    const int qc = lane & 3;

    float acc[2][4][4];
    #pragma unroll
    for (int i = 0; i < 2; i++)
        #pragma unroll
        for (int j = 0; j < 4; j++)
            #pragma unroll
            for (int r = 0; r < 4; r++) acc[i][j][r] = 0.f;

    for (int c = 0; c < NCH; c++) {
        const int buf = c & 1;
        if (c + 1 < NCH) {
            const int k0 = (c + 1) * KC;
            #pragma unroll
            for (int r = 0; r < 2; r++)
                xb[buf ^ 1][r] = *(const float4*)(Xg + k0 + (size_t)(64 * r) * DIM);
            wb[buf ^ 1][0] = *(const float4*)(Wg + k0);
        }

        uint32_t* sb = smw + (size_t)(c & 1) * STW;
        #pragma unroll
        for (int r = 0; r < 2; r++)
            store3(sb + (lrow + 64 * r) * RSTR + (lcol >> 1), XT_W, xb[buf][r]);
        store3(sb + WBASE + lrow * RSTR + (lcol >> 1), WT_W, wb[buf][0]);

        __syncthreads();

        const uint32_t* st = smw + (size_t)(c & 1) * STW;
        // one k16 step per warp (s = ks)
        uint32_t bf[3][4][2];
        #pragma unroll
        for (int ch = 0; ch < 3; ch++)
            #pragma unroll
            for (int j = 0; j < 4; j++) {
                const int base = WBASE + ch * WT_W
                               + (wn * 32 + j * 8 + qr) * RSTR + qc + 8 * ks;
                bf[ch][j][0] = st[base];
                bf[ch][j][1] = st[base + 4];
            }
        #pragma unroll
        for (int ch = 0; ch < 3; ch++) {
            uint32_t af[2][4];
            #pragma unroll
            for (int i = 0; i < 2; i++) {
                const int base = ch * XT_W
                               + (wm * 32 + i * 16 + qr) * RSTR + qc + 8 * ks;
                af[i][0] = st[base];
                af[i][1] = st[base + 8 * RSTR];
                af[i][2] = st[base + 4];
                af[i][3] = st[base + 8 * RSTR + 4];
            }
            const int nb = (ch == 0) ? 3 : ((ch == 1) ? 2 : 1);
            #pragma unroll
            for (int cb = 0; cb < 3; cb++) {
                if (cb < nb) {
                    #pragma unroll
                    for (int i = 0; i < 2; i++)
                        #pragma unroll
                        for (int j = 0; j < 4; j++)
                            MMA_BF16(acc[i][j], af[i], bf[cb][j]);
                }
            }
        }
        __syncthreads();   // stage reuse: consumers done before overwrite
    }

    // ---------------- K-split reduction + logits tile -----------------------
    float* lg    = (float*)smw;           // [128][65]
    float* sm_m  = lg + TM * 65;          // 8320
    float* sm_iv = sm_m + TM;             // 8448
    int*   scnt  = (int*)(sm_iv + TM);    // 8576
    float* zac   = (float*)(scnt + NEXP); // 8640
    float* scr   = lg + 8704;             // [128][65] partials from ks=1

    if (ks == 1) {
        #pragma unroll
        for (int i = 0; i < 2; i++)
            #pragma unroll
            for (int j = 0; j < 4; j++) {
                const int row = wm * 32 + i * 16 + qr;
                const int col = wn * 32 + j * 8 + 2 * qc;
                scr[ row      * 65 + col    ] = acc[i][j][0];
                scr[ row      * 65 + col + 1] = acc[i][j][1];
                scr[(row + 8) * 65 + col    ] = acc[i][j][2];
                scr[(row + 8) * 65 + col + 1] = acc[i][j][3];
            }
    }
    __syncthreads();
    if (ks == 0) {
        #pragma unroll
        for (int i = 0; i < 2; i++)
            #pragma unroll
            for (int j = 0; j < 4; j++) {
                const int row = wm * 32 + i * 16 + qr;
                const int col = wn * 32 + j * 8 + 2 * qc;
                lg[ row      * 65 + col    ] = acc[i][j][0] + scr[ row      * 65 + col    ];
                lg[ row      * 65 + col + 1] = acc[i][j][1] + scr[ row      * 65 + col + 1];
                lg[(row + 8) * 65 + col    ] = acc[i][j][2] + scr[(row + 8) * 65 + col    ];
                lg[(row + 8) * 65 + col + 1] = acc[i][j][3] + scr[(row + 8) * 65 + col + 1];
            }
    }
    if (tid < NEXP) scnt[tid] = 0;
    if (tid == 0) *zac = 0.f;
    __syncthreads();

    if (tid < TM) {
        const float* row = lg + tid * 65;

        // ---- approx top-4 (strict >, lowest index on ties) ----
        float tv[4] = {-3.4e38f, -3.4e38f, -3.4e38f, -3.4e38f};
        int   ti[4] = {0, 0, 0, 0};
        #pragma unroll
        for (int e = 0; e < NEXP; e++) {
            float v = row[e];
            if (v > tv[3]) {
                if (v > tv[0])      { tv[3]=tv[2]; ti[3]=ti[2]; tv[2]=tv[1]; ti[2]=ti[1]; tv[1]=tv[0]; ti[1]=ti[0]; tv[0]=v; ti[0]=e; }
                else if (v > tv[1]) { tv[3]=tv[2]; ti[3]=ti[2]; tv[2]=tv[1]; ti[2]=ti[1]; tv[1]=v;     ti[1]=e; }
                else if (v > tv[2]) { tv[3]=tv[2]; ti[3]=ti[2]; tv[2]=v;     ti[2]=e; }
                else                { tv[3]=v;     ti[3]=e; }
            }
        }

        const float am = tv[0];
        float sum = 0.f;
        #pragma unroll
        for (int e = 0; e < NEXP; e++) sum += __expf(row[e] - am);

        float m = tv[0], m2 = tv[1];
        int   i1 = ti[0], i2 = ti[1];

        // ---- near-tie: recompute candidates bit-exactly in R1's order ----
        if ((tv[0] - tv[1] < AMB_THR) || (tv[1] - tv[2] < AMB_THR)) {
            int ci[4] = {ti[0], ti[1], ti[2], ti[3]};
            #pragma unroll
            for (int a = 0; a < 3; a++)
                #pragma unroll
                for (int b = 0; b < 3 - a; b++)
                    if (ci[b] > ci[b + 1]) { int t = ci[b]; ci[b] = ci[b+1]; ci[b+1] = t; }

            const float* xr = X + (size_t)(tok0 + tid) * DIM;
            const float* w0 = W + (size_t)ci[0] * DIM;
            const float* w1 = W + (size_t)ci[1] * DIM;
            const float* w2 = W + (size_t)ci[2] * DIM;
            const float* w3 = W + (size_t)ci[3] * DIM;

            float aE[4] = {0.f, 0.f, 0.f, 0.f};
            float aO[4] = {0.f, 0.f, 0.f, 0.f};
            for (int k = 0; k < DIM; k += 8) {
                #pragma unroll
                for (int u = 0; u < 4; u++) {
                    const int ke = k + 2 * u, ko = ke + 1;
                    const float xe = xr[ke], xo = xr[ko];
                    aE[0] = __fmaf_rn(xe, w0[ke], aE[0]); aO[0] = __fmaf_rn(xo, w0[ko], aO[0]);
                    aE[1] = __fmaf_rn(xe, w1[ke], aE[1]); aO[1] = __fmaf_rn(xo, w1[ko], aO[1]);
                    aE[2] = __fmaf_rn(xe, w2[ke], aE[2]); aO[2] = __fmaf_rn(xo, w2[ko], aO[2]);
                    aE[3] = __fmaf_rn(xe, w3[ke], aE[3]); aO[3] = __fmaf_rn(xo, w3[ko], aO[3]);
                }
            }
            float lex[4];
            #pragma unroll
            for (int c2 = 0; c2 < 4; c2++) lex[c2] = aE[c2] + aO[c2];

            m = lex[0]; i1 = ci[0];
            #pragma unroll
            for (int c2 = 1; c2 < 4; c2++)
                if (lex[c2] > m) { m = lex[c2]; i1 = ci[c2]; }
            m2 = -3.4e38f; i2 = ci[0];
            #pragma unroll
            for (int c2 = 0; c2 < 4; c2++) {
                if (ci[c2] == i1) continue;
                if (lex[c2] > m2) { m2 = lex[c2]; i2 = ci[c2]; }
            }
        }

        const float e2 = __expf(m2 - m);
        const float r1 = 1.f / (1.f + e2);
        const float r2 = e2 * r1;

        const int tg = tok0 + tid;
        out[2 * tg + 0] = (float)i1;
        out[2 * tg + 1] = (float)i2;
        out[(size_t)2 * BS + 2 * tg + 0] = r1;
        out[(size_t)2 * BS + 2 * tg + 1] = r2;

        sm_m[tid]  = am;
        sm_iv[tid] = 1.f / sum;
        float lse = am + __logf(sum);
        atomicAdd(zac, lse * lse);
        atomicAdd(&scnt[i1], 1);
        atomicAdd(&scnt[i2], 1);
    }
    __syncthreads();

    if (tid < NEXP) {
        float p = 0.f;
        for (int t = 0; t < TM; t++)
            p += __expf(lg[t * 65 + tid] - sm_m[t]) * sm_iv[t];
        g_Pblk[blk * NEXP + tid]   = p;
        g_cntblk[blk * NEXP + tid] = scnt[tid];
    }
    if (tid == 0) g_zblk[blk] = *zac;

    __threadfence();
    __syncthreads();
    if (tid == 0) {
        unsigned v = atomicAdd(&g_arrival, 1u);
        s_flag = (v == (unsigned)(nblk - 1));
    }
    __syncthreads();

    if (s_flag) {
        __threadfence();
        float* sP = lg;
        float* sC = lg + NEXP;
        if (tid < NEXP) {
            float p = 0.f; int cnt = 0;
            for (int b = 0; b < nblk; b++) {
                p   += g_Pblk[b * NEXP + tid];
                cnt += g_cntblk[b * NEXP + tid];
            }
            sP[tid] = p; sC[tid] = (float)cnt;
        }
        __syncthreads();
        if (tid == 0) {
            float z = 0.f;
            for (int b = 0; b < nblk; b++) z += g_zblk[b];
            const float invBSK = 1.f / (2.f * (float)BS);
            const float invBS  = 1.f / (float)BS;
            float bal = 0.f;
            for (int e = 0; e < NEXP; e++)
                bal += (sC[e] * invBSK) * (sP[e] * invBS);
            bal *= (float)NEXP;
            float aux = 0.01f * bal + 0.001f * (z * invBS);
            for (int i = 4 * BS; i < out_size; i++) out[i] = aux;
            g_arrival = 0;
        }
    }
}

extern "C" void kernel_launch(void* const* d_in, const int* in_sizes, int n_in,
                              void* d_out, int out_size)
{
    const float* x = (const float*)d_in[0];
    const float* w = (const float*)d_in[1];
    float* out = (float*)d_out;

    const int Dv   = in_sizes[1] / NEXP;   // 2048
    const int BS   = in_sizes[0] / Dv;     // 16384
    const int nblk = BS / TM;              // 128

    const int smem = 2 * STW * (int)sizeof(uint32_t);   // 92160 B
    cudaFuncSetAttribute(router_bf16x3, cudaFuncAttributeMaxDynamicSharedMemorySize, smem);
    router_bf16x3<<<nblk, 512, smem>>>(x, w, out, BS, out_size, nblk);
}

// round 8
// speedup vs baseline: 1.0831x; 1.0740x over previous
#include <cuda_runtime.h>
#include <cstdint>

// ---------------------------------------------------------------------------
// TopKRouter: logits = x @ gate_w^T (16384 x 2048 x 64) via EXACT bf16x3
// split (6 products) on mma.sync.m16n8k16.bf16.
// R8 == R7 resubmit (container infra failure, kernel never ran):
// TM=64, 2 CTAs/SM, 3-stage smem ring, ONE barrier per chunk with
// produce/consume interleaved. Near-tie tokens re-derive candidate logits
// bit-exactly (R1 order). Single launch, deterministic reductions.
// Output (fp32): [top_indices (BS*2)] [top_weights (BS*2)] [aux ...fill]
// ---------------------------------------------------------------------------

#define NEXP 64
#define DIM  2048
#define KC   32                  // K per chunk
#define TM   64                  // tokens per CTA
#define NCH  (DIM / KC)          // 64 chunks
#define NSTG 3                   // smem ring stages
#define RSTR 20                  // row stride in words (80B): LDS conflict-free
#define XT_W (TM * RSTR)         // 1280 words per x chunk tile
#define WT_W (NEXP * RSTR)       // 1280 words per w chunk tile
#define WBASE (3 * XT_W)         // 3840
#define STW  (3 * XT_W + 3 * WT_W)   // 7680 words per stage (30720 B)
#define MAXBLK 256
#define AMB_THR 2e-5f

__device__ float    g_Pblk[MAXBLK * NEXP];
__device__ float    g_zblk[MAXBLK];
__device__ int      g_cntblk[MAXBLK * NEXP];
__device__ unsigned g_arrival;

#define MMA_BF16(d, a, b) \
    asm volatile("mma.sync.aligned.m16n8k16.row.col.f32.bf16.bf16.f32 " \
                 "{%0,%1,%2,%3}, {%4,%5,%6,%7}, {%8,%9}, {%0,%1,%2,%3};" \
                 : "+f"((d)[0]), "+f"((d)[1]), "+f"((d)[2]), "+f"((d)[3]) \
                 : "r"((a)[0]), "r"((a)[1]), "r"((a)[2]), "r"((a)[3]), \
                   "r"((b)[0]), "r"((b)[1]))

static __device__ __forceinline__ void split3(float v, uint32_t& c1, uint32_t& c2, uint32_t& c3) {
    uint32_t m1 = __float_as_uint(v) & 0xFFFF0000u;
    float r1 = v - __uint_as_float(m1);
    uint32_t m2 = __float_as_uint(r1) & 0xFFFF0000u;
    float r2 = r1 - __uint_as_float(m2);          // exact: v == c1+c2+c3
    c1 = m1; c2 = m2; c3 = __float_as_uint(r2);
}
static __device__ __forceinline__ uint32_t pk(uint32_t e, uint32_t o) {
    uint32_t d;
    asm("prmt.b32 %0, %1, %2, 0x7632;" : "=r"(d) : "r"(e), "r"(o));
    return d;
}
static __device__ __forceinline__ void store3(uint32_t* base0, int tile_w, float4 v) {
    uint32_t c1[4], c2[4], c3[4];
    split3(v.x, c1[0], c2[0], c3[0]);
    split3(v.y, c1[1], c2[1], c3[1]);
    split3(v.z, c1[2], c2[2], c3[2]);
    split3(v.w, c1[3], c2[3], c3[3]);
    *(uint2*)(base0 + 0 * tile_w) = make_uint2(pk(c1[0], c1[1]), pk(c1[2], c1[3]));
    *(uint2*)(base0 + 1 * tile_w) = make_uint2(pk(c2[0], c2[1]), pk(c2[2], c2[3]));
    *(uint2*)(base0 + 2 * tile_w) = make_uint2(pk(c3[0], c3[1]), pk(c3[2], c3[3]));
}

__global__ void __launch_bounds__(256, 2)
router_bf16x3(const float* __restrict__ X, const float* __restrict__ W,
              float* __restrict__ out, int BS, int out_size, int nblk)
{
    extern __shared__ uint32_t smw[];
    __shared__ int s_flag;

    const int tid  = threadIdx.x;
    const int wid  = tid >> 5;
    const int lane = tid & 31;
    const int blk  = blockIdx.x;
    const int tok0 = blk * TM;

    // ---- producer mapping: 256 thr; x: 2 float4 same row, w: same ----
    const int lrow = tid >> 2;            // 0..63
    const int lcol = (tid & 3) * 8;       // k offset 0,8,16,24
    const float* Xg = X + (size_t)(tok0 + lrow) * DIM + lcol;
    const float* Wg = W + (size_t)lrow * DIM + lcol;

    float4 xr[2][2], wr[2][2];

    // prologue: chunk0 -> regs[0] -> stage0 ; chunk1 -> regs[1]
    xr[0][0] = *(const float4*)(Xg);     xr[0][1] = *(const float4*)(Xg + 4);
    wr[0][0] = *(const float4*)(Wg);     wr[0][1] = *(const float4*)(Wg + 4);
    {
        uint32_t* sb = smw;               // stage 0
        store3(sb + lrow * RSTR + (lcol >> 1),     XT_W, xr[0][0]);
        store3(sb + lrow * RSTR + (lcol >> 1) + 2, XT_W, xr[0][1]);
        store3(sb + WBASE + lrow * RSTR + (lcol >> 1),     WT_W, wr[0][0]);
        store3(sb + WBASE + lrow * RSTR + (lcol >> 1) + 2, WT_W, wr[0][1]);
    }
    xr[1][0] = *(const float4*)(Xg + KC);     xr[1][1] = *(const float4*)(Xg + KC + 4);
    wr[1][0] = *(const float4*)(Wg + KC);     wr[1][1] = *(const float4*)(Wg + KC + 4);

    // ---- consumer mapping: 8 warps = 2m x 2n x 2k-split, tile m32n32 ----
    const int wm = wid & 1;
    const int wn = (wid >> 1) & 1;
    const int ks = wid >> 2;
    const int qr = lane >> 2;
    const int qc = lane & 3;

    float acc[2][4][4];
    #pragma unroll
    for (int i = 0; i < 2; i++)
        #pragma unroll
        for (int j = 0; j < 4; j++)
            #pragma unroll
            for (int r = 0; r < 4; r++) acc[i][j][r] = 0.f;

    for (int c = 0; c < NCH; c++) {
        __syncthreads();    // stage c fully written; stage (c+1)%3 free

        // produce stage c+1 from regs[(c+1)&1] (interleaves with consume below)
        if (c + 1 < NCH) {
            const int p = (c + 1) & 1;
            uint32_t* sb = smw + (size_t)((c + 1) % NSTG) * STW;
            store3(sb + lrow * RSTR + (lcol >> 1),     XT_W, xr[p][0]);
            store3(sb + lrow * RSTR + (lcol >> 1) + 2, XT_W, xr[p][1]);
            store3(sb + WBASE + lrow * RSTR + (lcol >> 1),     WT_W, wr[p][0]);
            store3(sb + WBASE + lrow * RSTR + (lcol >> 1) + 2, WT_W, wr[p][1]);
        }
        // prefetch chunk c+2 into regs[c&1]
        if (c + 2 < NCH) {
            const int p = c & 1;
            const int k0 = (c + 2) * KC;
            xr[p][0] = *(const float4*)(Xg + k0);  xr[p][1] = *(const float4*)(Xg + k0 + 4);
            wr[p][0] = *(const float4*)(Wg + k0);  wr[p][1] = *(const float4*)(Wg + k0 + 4);
        }

        // consume stage c (one k16 step per warp: s = ks)
        const uint32_t* st = smw + (size_t)(c % NSTG) * STW;
        uint32_t bf[3][4][2];
        #pragma unroll
        for (int ch = 0; ch < 3; ch++)
            #pragma unroll
            for (int j = 0; j < 4; j++) {
                const int base = WBASE + ch * WT_W
                               + (wn * 32 + j * 8 + qr) * RSTR + qc + 8 * ks;
                bf[ch][j][0] = st[base];
                bf[ch][j][1] = st[base + 4];
            }
        #pragma unroll
        for (int ch = 0; ch < 3; ch++) {
            uint32_t af[2][4];
            #pragma unroll
            for (int i = 0; i < 2; i++) {
                const int base = ch * XT_W
                               + (wm * 32 + i * 16 + qr) * RSTR + qc + 8 * ks;
                af[i][0] = st[base];
                af[i][1] = st[base + 8 * RSTR];
                af[i][2] = st[base + 4];
                af[i][3] = st[base + 8 * RSTR + 4];
            }
            const int nb = (ch == 0) ? 3 : ((ch == 1) ? 2 : 1);
            #pragma unroll
            for (int cb = 0; cb < 3; cb++) {
                if (cb < nb) {
                    #pragma unroll
                    for (int i = 0; i < 2; i++)
                        #pragma unroll
                        for (int j = 0; j < 4; j++)
                            MMA_BF16(acc[i][j], af[i], bf[cb][j]);
                }
            }
        }
    }
    __syncthreads();    // all consumption done before smem reuse

    // ---------------- K-split reduction + logits tile -----------------------
    float* lg    = (float*)smw;           // [64][65] = 4160 words
    float* sm_m  = lg + TM * 65;          // 4160
    float* sm_iv = sm_m + TM;             // 4224
    int*   scnt  = (int*)(sm_iv + TM);    // 4288
    float* zac   = (float*)(scnt + NEXP); // 4352
    float* scr   = lg + 8704;             // [64][65] ks=1 partials

    if (ks == 1) {
        #pragma unroll
        for (int i = 0; i < 2; i++)
            #pragma unroll
            for (int j = 0; j < 4; j++) {
                const int row = wm * 32 + i * 16 + qr;
                const int col = wn * 32 + j * 8 + 2 * qc;
                scr[ row      * 65 + col    ] = acc[i][j][0];
                scr[ row      * 65 + col + 1] = acc[i][j][1];
                scr[(row + 8) * 65 + col    ] = acc[i][j][2];
                scr[(row + 8) * 65 + col + 1] = acc[i][j][3];
            }
    }
    if (tid < NEXP) scnt[tid] = 0;
    if (tid == 0) *zac = 0.f;
    __syncthreads();
    if (ks == 0) {
        #pragma unroll
        for (int i = 0; i < 2; i++)
            #pragma unroll
            for (int j = 0; j < 4; j++) {
                const int row = wm * 32 + i * 16 + qr;
                const int col = wn * 32 + j * 8 + 2 * qc;
                lg[ row      * 65 + col    ] = acc[i][j][0] + scr[ row      * 65 + col    ];
                lg[ row      * 65 + col + 1] = acc[i][j][1] + scr[ row      * 65 + col + 1];
                lg[(row + 8) * 65 + col    ] = acc[i][j][2] + scr[(row + 8) * 65 + col    ];
                lg[(row + 8) * 65 + col + 1] = acc[i][j][3] + scr[(row + 8) * 65 + col + 1];
            }
    }
    __syncthreads();

    if (tid < TM) {
        const float* row = lg + tid * 65;

        // ---- approx top-4 (strict >, lowest index on ties) ----
        float tv[4] = {-3.4e38f, -3.4e38f, -3.4e38f, -3.4e38f};
        int   ti[4] = {0, 0, 0, 0};
        #pragma unroll
        for (int e = 0; e < NEXP; e++) {
            float v = row[e];
            if (v > tv[3]) {
                if (v > tv[0])      { tv[3]=tv[2]; ti[3]=ti[2]; tv[2]=tv[1]; ti[2]=ti[1]; tv[1]=tv[0]; ti[1]=ti[0]; tv[0]=v; ti[0]=e; }
                else if (v > tv[1]) { tv[3]=tv[2]; ti[3]=ti[2]; tv[2]=tv[1]; ti[2]=ti[1]; tv[1]=v;     ti[1]=e; }
                else if (v > tv[2]) { tv[3]=tv[2]; ti[3]=ti[2]; tv[2]=v;     ti[2]=e; }
                else                { tv[3]=v;     ti[3]=e; }
            }
        }

        const float am = tv[0];
        float sum = 0.f;
        #pragma unroll
        for (int e = 0; e < NEXP; e++) sum += __expf(row[e] - am);

        float m = tv[0], m2 = tv[1];
        int   i1 = ti[0], i2 = ti[1];

        // ---- near-tie: recompute candidates bit-exactly in R1's order ----
        if ((tv[0] - tv[1] < AMB_THR) || (tv[1] - tv[2] < AMB_THR)) {
            int ci[4] = {ti[0], ti[1], ti[2], ti[3]};
            #pragma unroll
            for (int a = 0; a < 3; a++)
                #pragma unroll
                for (int b = 0; b < 3 - a; b++)
                    if (ci[b] > ci[b + 1]) { int t = ci[b]; ci[b] = ci[b+1]; ci[b+1] = t; }

            const float* xp = X + (size_t)(tok0 + tid) * DIM;
            const float* w0 = W + (size_t)ci[0] * DIM;
            const float* w1 = W + (size_t)ci[1] * DIM;
            const float* w2 = W + (size_t)ci[2] * DIM;
            const float* w3 = W + (size_t)ci[3] * DIM;

            float aE[4] = {0.f, 0.f, 0.f, 0.f};
            float aO[4] = {0.f, 0.f, 0.f, 0.f};
            for (int k = 0; k < DIM; k += 8) {
                #pragma unroll
                for (int u = 0; u < 4; u++) {
                    const int ke = k + 2 * u, ko = ke + 1;
                    const float xe = xp[ke], xo = xp[ko];
                    aE[0] = __fmaf_rn(xe, w0[ke], aE[0]); aO[0] = __fmaf_rn(xo, w0[ko], aO[0]);
                    aE[1] = __fmaf_rn(xe, w1[ke], aE[1]); aO[1] = __fmaf_rn(xo, w1[ko], aO[1]);
                    aE[2] = __fmaf_rn(xe, w2[ke], aE[2]); aO[2] = __fmaf_rn(xo, w2[ko], aO[2]);
                    aE[3] = __fmaf_rn(xe, w3[ke], aE[3]); aO[3] = __fmaf_rn(xo, w3[ko], aO[3]);
                }
            }
            float lex[4];
            #pragma unroll
            for (int c2 = 0; c2 < 4; c2++) lex[c2] = aE[c2] + aO[c2];

            m = lex[0]; i1 = ci[0];
            #pragma unroll
            for (int c2 = 1; c2 < 4; c2++)
                if (lex[c2] > m) { m = lex[c2]; i1 = ci[c2]; }
            m2 = -3.4e38f; i2 = ci[0];
            #pragma unroll
            for (int c2 = 0; c2 < 4; c2++) {
                if (ci[c2] == i1) continue;
                if (lex[c2] > m2) { m2 = lex[c2]; i2 = ci[c2]; }
            }
        }

        const float e2 = __expf(m2 - m);
        const float r1 = 1.f / (1.f + e2);
        const float r2 = e2 * r1;

        const int tg = tok0 + tid;
        out[2 * tg + 0] = (float)i1;
        out[2 * tg + 1] = (float)i2;
        out[(size_t)2 * BS + 2 * tg + 0] = r1;
        out[(size_t)2 * BS + 2 * tg + 1] = r2;

        sm_m[tid]  = am;
        sm_iv[tid] = 1.f / sum;
        float lse = am + __logf(sum);
        atomicAdd(zac, lse * lse);
        atomicAdd(&scnt[i1], 1);
        atomicAdd(&scnt[i2], 1);
    }
    __syncthreads();

    if (tid < NEXP) {
        float p = 0.f;
        for (int t = 0; t < TM; t++)
            p += __expf(lg[t * 65 + tid] - sm_m[t]) * sm_iv[t];
        g_Pblk[blk * NEXP + tid]   = p;
        g_cntblk[blk * NEXP + tid] = scnt[tid];
    }
    if (tid == 0) g_zblk[blk] = *zac;

    __threadfence();
    __syncthreads();
    if (tid == 0) {
        unsigned v = atomicAdd(&g_arrival, 1u);
        s_flag = (v == (unsigned)(nblk - 1));
    }
    __syncthreads();

    if (s_flag) {                         // last block finalizes (fixed order)
        __threadfence();
        float* sP = lg;
        float* sC = lg + NEXP;
        if (tid < NEXP) {
            float p = 0.f; int cnt = 0;
            for (int b = 0; b < nblk; b++) {
                p   += g_Pblk[b * NEXP + tid];
                cnt += g_cntblk[b * NEXP + tid];
            }
            sP[tid] = p; sC[tid] = (float)cnt;
        }
        __syncthreads();
        if (tid == 0) {
            float z = 0.f;
            for (int b = 0; b < nblk; b++) z += g_zblk[b];
            const float invBSK = 1.f / (2.f * (float)BS);
            const float invBS  = 1.f / (float)BS;
            float bal = 0.f;
            for (int e = 0; e < NEXP; e++)
                bal += (sC[e] * invBSK) * (sP[e] * invBS);
            bal *= (float)NEXP;
            float aux = 0.01f * bal + 0.001f * (z * invBS);
            for (int i = 4 * BS; i < out_size; i++) out[i] = aux;
            g_arrival = 0;
        }
    }
}

extern "C" void kernel_launch(void* const* d_in, const int* in_sizes, int n_in,
                              void* d_out, int out_size)
{
    const float* x = (const float*)d_in[0];
    const float* w = (const float*)d_in[1];
    float* out = (float*)d_out;

    const int Dv   = in_sizes[1] / NEXP;   // 2048
    const int BS   = in_sizes[0] / Dv;     // 16384
    const int nblk = BS / TM;              // 256

    const int smem = NSTG * STW * (int)sizeof(uint32_t);   // 92160 B
    cudaFuncSetAttribute(router_bf16x3, cudaFuncAttributeMaxDynamicSharedMemorySize, smem);
    router_bf16x3<<<nblk, 256, smem>>>(x, w, out, BS, out_size, nblk);
}

// round 9
// speedup vs baseline: 1.2557x; 1.1594x over previous
#include <cuda_runtime.h>
#include <cuda_fp16.h>
#include <cstdint>

// ---------------------------------------------------------------------------
// TopKRouter: logits = x @ gate_w^T (16384 x 2048 x 64) via fp16 2-split
// (x=x1+x2, w=w1+w2, keep x1w1+x1w2+x2w1; dropped term ~2^-24 rel) on
// mma.sync.m16n8k16.f16 — 3 products (half the HMMA count of R8).
// TM=64, 2 CTAs/SM, 3-stage smem ring, one barrier per chunk, interleaved
// produce/consume. Near-tie tokens re-derive candidate logits bit-exactly
// (R1 order). Single launch, deterministic reductions.
// Output (fp32): [top_indices (BS*2)] [top_weights (BS*2)] [aux ...fill]
// ---------------------------------------------------------------------------

#define NEXP 64
#define DIM  2048
#define KC   32                  // K per chunk
#define TM   64                  // tokens per CTA
#define NCH  (DIM / KC)          // 64 chunks
#define NSTG 3                   // smem ring stages
#define RSTR 20                  // row stride in words (80B): LDS conflict-free
#define XT_W (TM * RSTR)         // 1280 words per x chunk tile
#define WT_W (NEXP * RSTR)       // 1280 words per w chunk tile
#define WBASE (2 * XT_W)         // 2560 (w tiles after 2 x tiles)
#define STW  (2 * XT_W + 2 * WT_W)   // 5120 words per stage (20480 B)
#define MAXBLK 256
#define AMB_THR 2e-5f

__device__ float    g_Pblk[MAXBLK * NEXP];
__device__ float    g_zblk[MAXBLK];
__device__ int      g_cntblk[MAXBLK * NEXP];
__device__ unsigned g_arrival;

#define MMA_F16(d, a, b) \
    asm volatile("mma.sync.aligned.m16n8k16.row.col.f32.f16.f16.f32 " \
                 "{%0,%1,%2,%3}, {%4,%5,%6,%7}, {%8,%9}, {%0,%1,%2,%3};" \
                 : "+f"((d)[0]), "+f"((d)[1]), "+f"((d)[2]), "+f"((d)[3]) \
                 : "r"((a)[0]), "r"((a)[1]), "r"((a)[2]), "r"((a)[3]), \
                   "r"((b)[0]), "r"((b)[1]))

static __device__ __forceinline__ uint32_t h2u(__half2 h) {
    return *reinterpret_cast<uint32_t*>(&h);
}
// fp16 2-way split of 4 consecutive k-values: writes hi word-pair to chunk
// tile 0 and residual word-pair to chunk tile 1. low half of each word =
// lower k (matches m16n8k16 fragment layout).
static __device__ __forceinline__ void store2(uint32_t* b, int tile_w, float4 v) {
    __half2 h1a = __floats2half2_rn(v.x, v.y);
    __half2 h1b = __floats2half2_rn(v.z, v.w);
    float2  f1a = __half22float2(h1a);
    float2  f1b = __half22float2(h1b);
    __half2 h2a = __floats2half2_rn(v.x - f1a.x, v.y - f1a.y);
    __half2 h2b = __floats2half2_rn(v.z - f1b.x, v.w - f1b.y);
    *(uint2*)(b + 0 * tile_w) = make_uint2(h2u(h1a), h2u(h1b));
    *(uint2*)(b + 1 * tile_w) = make_uint2(h2u(h2a), h2u(h2b));
}

__global__ void __launch_bounds__(256, 2)
router_f16x2(const float* __restrict__ X, const float* __restrict__ W,
             float* __restrict__ out, int BS, int out_size, int nblk)
{
    extern __shared__ uint32_t smw[];
    __shared__ int s_flag;

    const int tid  = threadIdx.x;
    const int wid  = tid >> 5;
    const int lane = tid & 31;
    const int blk  = blockIdx.x;
    const int tok0 = blk * TM;

    // ---- producer mapping: 256 thr; x: 2 float4 same row, w: same ----
    const int lrow = tid >> 2;            // 0..63
    const int lcol = (tid & 3) * 8;       // k offset 0,8,16,24
    const float* Xg = X + (size_t)(tok0 + lrow) * DIM + lcol;
    const float* Wg = W + (size_t)lrow * DIM + lcol;

    float4 xr[2][2], wr[2][2];

    // prologue: chunk0 -> regs[0] -> stage0 ; chunk1 -> regs[1]
    xr[0][0] = *(const float4*)(Xg);     xr[0][1] = *(const float4*)(Xg + 4);
    wr[0][0] = *(const float4*)(Wg);     wr[0][1] = *(const float4*)(Wg + 4);
    {
        uint32_t* sb = smw;               // stage 0
        store2(sb + lrow * RSTR + (lcol >> 1),     XT_W, xr[0][0]);
        store2(sb + lrow * RSTR + (lcol >> 1) + 2, XT_W, xr[0][1]);
        store2(sb + WBASE + lrow * RSTR + (lcol >> 1),     WT_W, wr[0][0]);
        store2(sb + WBASE + lrow * RSTR + (lcol >> 1) + 2, WT_W, wr[0][1]);
    }
    xr[1][0] = *(const float4*)(Xg + KC);     xr[1][1] = *(const float4*)(Xg + KC + 4);
    wr[1][0] = *(const float4*)(Wg + KC);     wr[1][1] = *(const float4*)(Wg + KC + 4);

    // ---- consumer mapping: 8 warps = 2m x 2n x 2k-split, tile m32n32 ----
    const int wm = wid & 1;
    const int wn = (wid >> 1) & 1;
    const int ks = wid >> 2;
    const int qr = lane >> 2;
    const int qc = lane & 3;

    float acc[2][4][4];
    #pragma unroll
    for (int i = 0; i < 2; i++)
        #pragma unroll
        for (int j = 0; j < 4; j++)
            #pragma unroll
            for (int r = 0; r < 4; r++) acc[i][j][r] = 0.f;

    for (int c = 0; c < NCH; c++) {
        __syncthreads();    // stage c fully written; stage (c+1)%3 free

        // produce stage c+1 from regs[(c+1)&1] (interleaves with consume)
        if (c + 1 < NCH) {
            const int p = (c + 1) & 1;
            uint32_t* sb = smw + (size_t)((c + 1) % NSTG) * STW;
            store2(sb + lrow * RSTR + (lcol >> 1),     XT_W, xr[p][0]);
            store2(sb + lrow * RSTR + (lcol >> 1) + 2, XT_W, xr[p][1]);
            store2(sb + WBASE + lrow * RSTR + (lcol >> 1),     WT_W, wr[p][0]);
            store2(sb + WBASE + lrow * RSTR + (lcol >> 1) + 2, WT_W, wr[p][1]);
        }
        // prefetch chunk c+2 into regs[c&1]
        if (c + 2 < NCH) {
            const int p = c & 1;
            const int k0 = (c + 2) * KC;
            xr[p][0] = *(const float4*)(Xg + k0);  xr[p][1] = *(const float4*)(Xg + k0 + 4);
            wr[p][0] = *(const float4*)(Wg + k0);  wr[p][1] = *(const float4*)(Wg + k0 + 4);
        }

        // consume stage c (one k16 step per warp: s = ks)
        const uint32_t* st = smw + (size_t)(c % NSTG) * STW;
        uint32_t bf[2][4][2];
        #pragma unroll
        for (int ch = 0; ch < 2; ch++)
            #pragma unroll
            for (int j = 0; j < 4; j++) {
                const int base = WBASE + ch * WT_W
                               + (wn * 32 + j * 8 + qr) * RSTR + qc + 8 * ks;
                bf[ch][j][0] = st[base];
                bf[ch][j][1] = st[base + 4];
            }
        uint32_t af[2][2][4];
        #pragma unroll
        for (int ch = 0; ch < 2; ch++)
            #pragma unroll
            for (int i = 0; i < 2; i++) {
                const int base = ch * XT_W
                               + (wm * 32 + i * 16 + qr) * RSTR + qc + 8 * ks;
                af[ch][i][0] = st[base];
                af[ch][i][1] = st[base + 8 * RSTR];
                af[ch][i][2] = st[base + 4];
                af[ch][i][3] = st[base + 8 * RSTR + 4];
            }
        // 3 products: x1w1, x1w2, x2w1 (fixed order -> deterministic)
        #pragma unroll
        for (int i = 0; i < 2; i++)
            #pragma unroll
            for (int j = 0; j < 4; j++) {
                MMA_F16(acc[i][j], af[0][i], bf[0][j]);
                MMA_F16(acc[i][j], af[0][i], bf[1][j]);
                MMA_F16(acc[i][j], af[1][i], bf[0][j]);
            }
    }
    __syncthreads();    // all consumption done before smem reuse

    // ---------------- K-split reduction + logits tile -----------------------
    float* lg    = (float*)smw;           // [64][65] = 4160 words
    float* sm_m  = lg + TM * 65;          // 4160
    float* sm_iv = sm_m + TM;             // 4224
    int*   scnt  = (int*)(sm_iv + TM);    // 4288
    float* zac   = (float*)(scnt + NEXP); // 4352
    float* scr   = lg + 4416;             // [64][65] ks=1 partials (4416..8576)

    if (ks == 1) {
        #pragma unroll
        for (int i = 0; i < 2; i++)
            #pragma unroll
            for (int j = 0; j < 4; j++) {
                const int row = wm * 32 + i * 16 + qr;
                const int col = wn * 32 + j * 8 + 2 * qc;
                scr[ row      * 65 + col    ] = acc[i][j][0];
                scr[ row      * 65 + col + 1] = acc[i][j][1];
                scr[(row + 8) * 65 + col    ] = acc[i][j][2];
                scr[(row + 8) * 65 + col + 1] = acc[i][j][3];
            }
    }
    if (tid < NEXP) scnt[tid] = 0;
    if (tid == 0) *zac = 0.f;
    __syncthreads();
    if (ks == 0) {
        #pragma unroll
        for (int i = 0; i < 2; i++)
            #pragma unroll
            for (int j = 0; j < 4; j++) {
                const int row = wm * 32 + i * 16 + qr;
                const int col = wn * 32 + j * 8 + 2 * qc;
                lg[ row      * 65 + col    ] = acc[i][j][0] + scr[ row      * 65 + col    ];
                lg[ row      * 65 + col + 1] = acc[i][j][1] + scr[ row      * 65 + col + 1];
                lg[(row + 8) * 65 + col    ] = acc[i][j][2] + scr[(row + 8) * 65 + col    ];
                lg[(row + 8) * 65 + col + 1] = acc[i][j][3] + scr[(row + 8) * 65 + col + 1];
            }
    }
    __syncthreads();

    if (tid < TM) {
        const float* row = lg + tid * 65;

        // ---- approx top-4 (strict >, lowest index on ties) ----
        float tv[4] = {-3.4e38f, -3.4e38f, -3.4e38f, -3.4e38f};
        int   ti[4] = {0, 0, 0, 0};
        #pragma unroll
        for (int e = 0; e < NEXP; e++) {
            float v = row[e];
            if (v > tv[3]) {
                if (v > tv[0])      { tv[3]=tv[2]; ti[3]=ti[2]; tv[2]=tv[1]; ti[2]=ti[1]; tv[1]=tv[0]; ti[1]=ti[0]; tv[0]=v; ti[0]=e; }
                else if (v > tv[1]) { tv[3]=tv[2]; ti[3]=ti[2]; tv[2]=tv[1]; ti[2]=ti[1]; tv[1]=v;     ti[1]=e; }
                else if (v > tv[2]) { tv[3]=tv[2]; ti[3]=ti[2]; tv[2]=v;     ti[2]=e; }
                else                { tv[3]=v;     ti[3]=e; }
            }
        }

        const float am = tv[0];
        float sum = 0.f;
        #pragma unroll
        for (int e = 0; e < NEXP; e++) sum += __expf(row[e] - am);

        float m = tv[0], m2 = tv[1];
        int   i1 = ti[0], i2 = ti[1];

        // ---- near-tie: recompute candidates bit-exactly in R1's order ----
        if ((tv[0] - tv[1] < AMB_THR) || (tv[1] - tv[2] < AMB_THR)) {
            int ci[4] = {ti[0], ti[1], ti[2], ti[3]};
            #pragma unroll
            for (int a = 0; a < 3; a++)
                #pragma unroll
                for (int b = 0; b < 3 - a; b++)
                    if (ci[b] > ci[b + 1]) { int t = ci[b]; ci[b] = ci[b+1]; ci[b+1] = t; }

            const float* xp = X + (size_t)(tok0 + tid) * DIM;
            const float* w0 = W + (size_t)ci[0] * DIM;
            const float* w1 = W + (size_t)ci[1] * DIM;
            const float* w2 = W + (size_t)ci[2] * DIM;
            const float* w3 = W + (size_t)ci[3] * DIM;

            float aE[4] = {0.f, 0.f, 0.f, 0.f};
            float aO[4] = {0.f, 0.f, 0.f, 0.f};
            for (int k = 0; k < DIM; k += 8) {
                #pragma unroll
                for (int u = 0; u < 4; u++) {
                    const int ke = k + 2 * u, ko = ke + 1;
                    const float xe = xp[ke], xo = xp[ko];
                    aE[0] = __fmaf_rn(xe, w0[ke], aE[0]); aO[0] = __fmaf_rn(xo, w0[ko], aO[0]);
                    aE[1] = __fmaf_rn(xe, w1[ke], aE[1]); aO[1] = __fmaf_rn(xo, w1[ko], aO[1]);
                    aE[2] = __fmaf_rn(xe, w2[ke], aE[2]); aO[2] = __fmaf_rn(xo, w2[ko], aO[2]);
                    aE[3] = __fmaf_rn(xe, w3[ke], aE[3]); aO[3] = __fmaf_rn(xo, w3[ko], aO[3]);
                }
            }
            float lex[4];
            #pragma unroll
            for (int c2 = 0; c2 < 4; c2++) lex[c2] = aE[c2] + aO[c2];

            m = lex[0]; i1 = ci[0];
            #pragma unroll
            for (int c2 = 1; c2 < 4; c2++)
                if (lex[c2] > m) { m = lex[c2]; i1 = ci[c2]; }
            m2 = -3.4e38f; i2 = ci[0];
            #pragma unroll
            for (int c2 = 0; c2 < 4; c2++) {
                if (ci[c2] == i1) continue;
                if (lex[c2] > m2) { m2 = lex[c2]; i2 = ci[c2]; }
            }
        }

        const float e2 = __expf(m2 - m);
        const float r1 = 1.f / (1.f + e2);
        const float r2 = e2 * r1;

        const int tg = tok0 + tid;
        out[2 * tg + 0] = (float)i1;
        out[2 * tg + 1] = (float)i2;
        out[(size_t)2 * BS + 2 * tg + 0] = r1;
        out[(size_t)2 * BS + 2 * tg + 1] = r2;

        sm_m[tid]  = am;
        sm_iv[tid] = 1.f / sum;
        float lse = am + __logf(sum);
        atomicAdd(zac, lse * lse);
        atomicAdd(&scnt[i1], 1);
        atomicAdd(&scnt[i2], 1);
    }
    __syncthreads();

    if (tid < NEXP) {
        float p = 0.f;
        for (int t = 0; t < TM; t++)
            p += __expf(lg[t * 65 + tid] - sm_m[t]) * sm_iv[t];
        g_Pblk[blk * NEXP + tid]   = p;
        g_cntblk[blk * NEXP + tid] = scnt[tid];
    }
    if (tid == 0) g_zblk[blk] = *zac;

    __threadfence();
    __syncthreads();
    if (tid == 0) {
        unsigned v = atomicAdd(&g_arrival, 1u);
        s_flag = (v == (unsigned)(nblk - 1));
    }
    __syncthreads();

    if (s_flag) {                         // last block finalizes (fixed order)
        __threadfence();
        float* sP = lg;
        float* sC = lg + NEXP;
        if (tid < NEXP) {
            float p = 0.f; int cnt = 0;
            for (int b = 0; b < nblk; b++) {
                p   += g_Pblk[b * NEXP + tid];
                cnt += g_cntblk[b * NEXP + tid];
            }
            sP[tid] = p; sC[tid] = (float)cnt;
        }
        __syncthreads();
        if (tid == 0) {
            float z = 0.f;
            for (int b = 0; b < nblk; b++) z += g_zblk[b];
            const float invBSK = 1.f / (2.f * (float)BS);
            const float invBS  = 1.f / (float)BS;
            float bal = 0.f;
            for (int e = 0; e < NEXP; e++)
                bal += (sC[e] * invBSK) * (sP[e] * invBS);
            bal *= (float)NEXP;
            float aux = 0.01f * bal + 0.001f * (z * invBS);
            for (int i = 4 * BS; i < out_size; i++) out[i] = aux;
            g_arrival = 0;
        }
    }
}

extern "C" void kernel_launch(void* const* d_in, const int* in_sizes, int n_in,
                              void* d_out, int out_size)
{
    const float* x = (const float*)d_in[0];
    const float* w = (const float*)d_in[1];
    float* out = (float*)d_out;

    const int Dv   = in_sizes[1] / NEXP;   // 2048
    const int BS   = in_sizes[0] / Dv;     // 16384
    const int nblk = BS / TM;              // 256

    const int smem = NSTG * STW * (int)sizeof(uint32_t);   // 61440 B
    cudaFuncSetAttribute(router_f16x2, cudaFuncAttributeMaxDynamicSharedMemorySize, smem);
    router_f16x2<<<nblk, 256, smem>>>(x, w, out, BS, out_size, nblk);
}